// round 7
// baseline (speedup 1.0000x reference)
#include <cuda_runtime.h>
#include <math.h>
#include <stdint.h>

#define B_ 4
#define L_ 1024
#define D_ 1024
#define H_ 16
#define HD_ 64
#define D3_ 3072
#define ADJW (L_/32)

// Scratch (device globals: allocation-free rule)
__device__ float g_qkv[B_*L_*D3_];            // 48 MB   [B,L,3D]
__device__ float g_attn[B_*L_*D_];            // 16 MB   [B,L,D]
__device__ unsigned g_adj[L_*ADJW];           // 128 KB  bitmask

// ---------------------------------------------------------------------------
// Helpers
// ---------------------------------------------------------------------------
__device__ __forceinline__ uint32_t f2tf32(float x) {
    uint32_t r;
    asm("cvt.rna.tf32.f32 %0, %1;" : "=r"(r) : "f"(x));
    return r;
}

__device__ __forceinline__ void mma_tf32(float* d, const uint32_t* a, const uint32_t* b) {
    asm volatile(
        "mma.sync.aligned.m16n8k8.row.col.f32.tf32.tf32.f32 "
        "{%0,%1,%2,%3}, {%4,%5,%6,%7}, {%8,%9}, {%0,%1,%2,%3};"
        : "+f"(d[0]), "+f"(d[1]), "+f"(d[2]), "+f"(d[3])
        : "r"(a[0]), "r"(a[1]), "r"(a[2]), "r"(a[3]),
          "r"(b[0]), "r"(b[1]));
}

__device__ __forceinline__ void cp_async16(void* dst, const void* src) {
    uint32_t d = (uint32_t)__cvta_generic_to_shared(dst);
    asm volatile("cp.async.cg.shared.global [%0], [%1], 16;\n" :: "r"(d), "l"(src));
}
__device__ __forceinline__ void cp_commit() {
    asm volatile("cp.async.commit_group;\n");
}
template<int N>
__device__ __forceinline__ void cp_wait() {
    asm volatile("cp.async.wait_group %0;\n" :: "n"(N));
}

// ---------------------------------------------------------------------------
// Adjacency build
// ---------------------------------------------------------------------------
__global__ void zero_adj_kernel(unsigned* adj) {
    int i = blockIdx.x * blockDim.x + threadIdx.x;
    if (i < L_*ADJW) adj[i] = 0u;
}

__global__ void build_adj_kernel(unsigned* adj, const int* __restrict__ edges, int E) {
    int e = blockIdx.x * blockDim.x + threadIdx.x;
    if (e < E) {
        int i = edges[2*e], j = edges[2*e+1];
        atomicOr(&adj[i*ADJW + (j >> 5)], 1u << (j & 31));
        atomicOr(&adj[j*ADJW + (i >> 5)], 1u << (i & 31));
    }
}

// ---------------------------------------------------------------------------
// 3-stage cp.async pipelined tf32 GEMM.
//   C[m,n] = sum_k A[m*lda+k] * B[n*ldb+k] + bias[n]       (B always K-major)
// Tiles stored RAW f32 row-major (cp.async), cvt.rna.tf32 at fragment load
// (numerically identical to converting at store time).
// Row stride BK+4=36 words == 4 (mod 32): fragment bank = 4*lr+lc, all 32
// lanes distinct -> conflict-free LDS.
// ---------------------------------------------------------------------------
template<int BM, int BN, int BK, int WM, int WN>
__global__ void __launch_bounds__(WM*WN*32)
gemm_tc_pipe(const float* __restrict__ A, const float* __restrict__ Bm,
             const float* __restrict__ bias, float* __restrict__ C,
             int lda, int ldb, int ldc, int K)
{
    constexpr int NT  = WM*WN*32;
    constexpr int WTM = BM/WM;      // 64
    constexpr int WTN = BN/WN;      // 32
    constexpr int MI  = WTM/16;     // 4
    constexpr int NI  = WTN/8;      // 4
    constexpr int BKP = BK + 4;     // 36
    constexpr int ST  = 3;

    extern __shared__ float smg[];
    float (*As)[BM][BKP] = (float(*)[BM][BKP])smg;
    float (*Bs)[BN][BKP] = (float(*)[BN][BKP])(smg + ST*BM*BKP);

    const int tid  = threadIdx.x;
    const int wid  = tid >> 5;
    const int lane = tid & 31;
    const int wm   = wid / WN;
    const int wn   = wid % WN;
    const int m0   = blockIdx.y * BM;
    const int n0   = blockIdx.x * BN;
    const int lr   = lane >> 2;
    const int lc   = lane & 3;

    constexpr int CP  = BK/4;       // 8 float4 per row
    constexpr int RPP = NT / CP;    // 32 rows per pass
    const int lrow = tid / CP;
    const int lcol = (tid % CP) * 4;

    // stage loader
    auto load_stage = [&](int s, int k0) {
        #pragma unroll
        for (int p = 0; p < BM/RPP; p++) {
            int r = lrow + p * RPP;
            cp_async16(&As[s][r][lcol], A + (long)(m0 + r) * lda + k0 + lcol);
        }
        #pragma unroll
        for (int p = 0; p < BN/RPP; p++) {
            int r = lrow + p * RPP;
            cp_async16(&Bs[s][r][lcol], Bm + (long)(n0 + r) * ldb + k0 + lcol);
        }
    };

    float acc[MI][NI][4];
    #pragma unroll
    for (int i = 0; i < MI; i++)
        #pragma unroll
        for (int j = 0; j < NI; j++)
            #pragma unroll
            for (int r = 0; r < 4; r++) acc[i][j][r] = 0.0f;

    const int NKI = K / BK;
    load_stage(0, 0);        cp_commit();
    load_stage(1, BK);       cp_commit();

    for (int ki = 0; ki < NKI; ki++) {
        cp_wait<1>();
        __syncthreads();

        if (ki + 2 < NKI) load_stage((ki + 2) % ST, (ki + 2) * BK);
        cp_commit();        // commit every iter (possibly empty) -> wait<1> is exact

        const int s = ki % ST;
        #pragma unroll
        for (int kk = 0; kk < BK; kk += 8) {
            uint32_t af[MI][4], bf[NI][2];
            #pragma unroll
            for (int i = 0; i < MI; i++) {
                const int mmx = wm*WTM + i*16;
                af[i][0] = f2tf32(As[s][mmx+lr  ][kk+lc  ]);
                af[i][1] = f2tf32(As[s][mmx+lr+8][kk+lc  ]);
                af[i][2] = f2tf32(As[s][mmx+lr  ][kk+lc+4]);
                af[i][3] = f2tf32(As[s][mmx+lr+8][kk+lc+4]);
            }
            #pragma unroll
            for (int j = 0; j < NI; j++) {
                const int nn = wn*WTN + j*8;
                bf[j][0] = f2tf32(Bs[s][nn+lr][kk+lc  ]);
                bf[j][1] = f2tf32(Bs[s][nn+lr][kk+lc+4]);
            }
            #pragma unroll
            for (int i = 0; i < MI; i++)
                #pragma unroll
                for (int j = 0; j < NI; j++)
                    mma_tf32(acc[i][j], af[i], bf[j]);
        }
    }

    // ---- epilogue
    #pragma unroll
    for (int i = 0; i < MI; i++) {
        #pragma unroll
        for (int j = 0; j < NI; j++) {
            const int mmx = m0 + wm*WTM + i*16 + lr;
            const int nn  = n0 + wn*WTN + j*8 + lc*2;
            float2 v0 = make_float2(acc[i][j][0], acc[i][j][1]);
            float2 v1 = make_float2(acc[i][j][2], acc[i][j][3]);
            const float2 bb = *(const float2*)(bias + nn);
            v0.x += bb.x; v0.y += bb.y;
            v1.x += bb.x; v1.y += bb.y;
            *(float2*)(C + (long)mmx * ldc + nn)     = v0;
            *(float2*)(C + (long)(mmx+8) * ldc + nn) = v1;
        }
    }
}

#define GEMM_SMEM (3 * (128*36 + 128*36) * 4)

// ---------------------------------------------------------------------------
// Fused flash attention with graph mask (unchanged from R6).
// ---------------------------------------------------------------------------
#define FL_SMEM ((128*68 + 64*68 + 64*72 + 128*68) * 4)

__global__ void __launch_bounds__(256, 2)
flash_kernel(const float* __restrict__ qkv, const unsigned* __restrict__ adj,
             float* __restrict__ attn_out)
{
    extern __shared__ uint32_t smf[];
    uint32_t (*Qs)[68] = (uint32_t(*)[68])(smf);                              // [qrow][hd]
    uint32_t (*Ks)[68] = (uint32_t(*)[68])(smf + 128*68);                     // [key][hd]
    uint32_t (*Vs)[72] = (uint32_t(*)[72])(smf + 128*68 + 64*68);             // [key][hd]
    uint32_t (*Ps)[68] = (uint32_t(*)[68])(smf + 128*68 + 64*68 + 64*72);     // [qrow][key]

    const int q0 = blockIdx.x * 128;
    const int b  = blockIdx.y / H_;
    const int h  = blockIdx.y % H_;

    const int tid  = threadIdx.x;
    const int wid  = tid >> 5;
    const int lane = tid & 31;
    const int lr   = lane >> 2;
    const int lc   = lane & 3;
    const int mm   = wid * 16;

    const float* qb = qkv + (long)b*L_*D3_ + h*HD_;
    const float* kb = qb + D_;
    const float* vb = qb + 2*D_;

    // ---- Q tile (pre-scaled by 1/sqrt(64) = 0.125)
    {
        const int r  = tid >> 4;
        const int c4 = (tid & 15) * 4;
        #pragma unroll
        for (int p = 0; p < 8; p++) {
            const float4 v = *(const float4*)(qb + (long)(q0 + r + p*16)*D3_ + c4);
            Qs[r+p*16][c4+0] = f2tf32(v.x * 0.125f);
            Qs[r+p*16][c4+1] = f2tf32(v.y * 0.125f);
            Qs[r+p*16][c4+2] = f2tf32(v.z * 0.125f);
            Qs[r+p*16][c4+3] = f2tf32(v.w * 0.125f);
        }
    }

    const int r0g = q0 + mm + lr;
    const int r1g = r0g + 8;
    const unsigned* adj0 = adj + (long)r0g * ADJW;
    const unsigned* adj1 = adj + (long)r1g * ADJW;

    float o[8][4];
    #pragma unroll
    for (int j = 0; j < 8; j++)
        #pragma unroll
        for (int r = 0; r < 4; r++) o[j][r] = 0.0f;
    float m0 = -INFINITY, m1 = -INFINITY, l0 = 0.0f, l1 = 0.0f;

    for (int kt = 0; kt < 16; kt++) {
        const int kbase = kt * 64;
        {
            const int r  = tid >> 4;
            const int c4 = (tid & 15) * 4;
            #pragma unroll
            for (int p = 0; p < 4; p++) {
                const long row = (long)(kbase + r + p*16) * D3_;
                const float4 kv = *(const float4*)(kb + row + c4);
                Ks[r+p*16][c4+0] = f2tf32(kv.x); Ks[r+p*16][c4+1] = f2tf32(kv.y);
                Ks[r+p*16][c4+2] = f2tf32(kv.z); Ks[r+p*16][c4+3] = f2tf32(kv.w);
                const float4 vv = *(const float4*)(vb + row + c4);
                Vs[r+p*16][c4+0] = f2tf32(vv.x); Vs[r+p*16][c4+1] = f2tf32(vv.y);
                Vs[r+p*16][c4+2] = f2tf32(vv.z); Vs[r+p*16][c4+3] = f2tf32(vv.w);
            }
        }
        __syncthreads();

        // ---- S = (Q/8) K^T : warp tile 16 x 64
        float sc[8][4];
        #pragma unroll
        for (int j = 0; j < 8; j++)
            #pragma unroll
            for (int r = 0; r < 4; r++) sc[j][r] = 0.0f;

        #pragma unroll
        for (int kk = 0; kk < 64; kk += 8) {
            uint32_t af[4];
            af[0] = Qs[mm+lr  ][kk+lc  ];
            af[1] = Qs[mm+lr+8][kk+lc  ];
            af[2] = Qs[mm+lr  ][kk+lc+4];
            af[3] = Qs[mm+lr+8][kk+lc+4];
            #pragma unroll
            for (int j = 0; j < 8; j++) {
                uint32_t bf[2];
                bf[0] = Ks[8*j+lr][kk+lc  ];
                bf[1] = Ks[8*j+lr][kk+lc+4];
                mma_tf32(sc[j], af, bf);
            }
        }

        // ---- mask + online softmax
        const unsigned wA0 = adj0[2*kt], wA1 = adj0[2*kt+1];
        const unsigned wB0 = adj1[2*kt], wB1 = adj1[2*kt+1];
        float tm0 = -INFINITY, tm1 = -INFINITY;
        unsigned mk = 0;
        #pragma unroll
        for (int j = 0; j < 8; j++) {
            const int cbit = (8*j + 2*lc) & 31;
            const unsigned wa = (j < 4) ? wA0 : wA1;
            const unsigned wb = (j < 4) ? wB0 : wB1;
            const unsigned f00 = (wa >> cbit) & 1u;
            const unsigned f01 = (wa >> (cbit+1)) & 1u;
            const unsigned f10 = (wb >> cbit) & 1u;
            const unsigned f11 = (wb >> (cbit+1)) & 1u;
            mk |= (f00 | (f01 << 1) | (f10 << 2) | (f11 << 3)) << (4*j);
            if (!f00) tm0 = fmaxf(tm0, sc[j][0]);
            if (!f01) tm0 = fmaxf(tm0, sc[j][1]);
            if (!f10) tm1 = fmaxf(tm1, sc[j][2]);
            if (!f11) tm1 = fmaxf(tm1, sc[j][3]);
        }
        tm0 = fmaxf(tm0, __shfl_xor_sync(0xFFFFFFFFu, tm0, 1));
        tm0 = fmaxf(tm0, __shfl_xor_sync(0xFFFFFFFFu, tm0, 2));
        tm1 = fmaxf(tm1, __shfl_xor_sync(0xFFFFFFFFu, tm1, 1));
        tm1 = fmaxf(tm1, __shfl_xor_sync(0xFFFFFFFFu, tm1, 2));

        const float mn0 = fmaxf(m0, tm0);
        const float mn1 = fmaxf(m1, tm1);
        const float a0 = (m0 == -INFINITY) ? 0.0f : __expf(m0 - mn0);
        const float a1 = (m1 == -INFINITY) ? 0.0f : __expf(m1 - mn1);
        m0 = mn0; m1 = mn1;

        float rs0 = 0.0f, rs1 = 0.0f;
        #pragma unroll
        for (int j = 0; j < 8; j++) {
            const unsigned mj = mk >> (4*j);
            const float p0 = (mj & 1u) ? 0.0f : __expf(sc[j][0] - mn0);
            const float p1 = (mj & 2u) ? 0.0f : __expf(sc[j][1] - mn0);
            const float p2 = (mj & 4u) ? 0.0f : __expf(sc[j][2] - mn1);
            const float p3 = (mj & 8u) ? 0.0f : __expf(sc[j][3] - mn1);
            rs0 += p0 + p1;
            rs1 += p2 + p3;
            Ps[mm+lr  ][8*j+2*lc  ] = f2tf32(p0);
            Ps[mm+lr  ][8*j+2*lc+1] = f2tf32(p1);
            Ps[mm+lr+8][8*j+2*lc  ] = f2tf32(p2);
            Ps[mm+lr+8][8*j+2*lc+1] = f2tf32(p3);
        }
        rs0 += __shfl_xor_sync(0xFFFFFFFFu, rs0, 1);
        rs0 += __shfl_xor_sync(0xFFFFFFFFu, rs0, 2);
        rs1 += __shfl_xor_sync(0xFFFFFFFFu, rs1, 1);
        rs1 += __shfl_xor_sync(0xFFFFFFFFu, rs1, 2);
        l0 = a0*l0 + rs0;
        l1 = a1*l1 + rs1;

        #pragma unroll
        for (int j = 0; j < 8; j++) {
            o[j][0] *= a0; o[j][1] *= a0;
            o[j][2] *= a1; o[j][3] *= a1;
        }

        __syncwarp();

        // ---- O += P V : m16 n64 k64
        #pragma unroll
        for (int kk = 0; kk < 64; kk += 8) {
            uint32_t af[4];
            af[0] = Ps[mm+lr  ][kk+lc  ];
            af[1] = Ps[mm+lr+8][kk+lc  ];
            af[2] = Ps[mm+lr  ][kk+lc+4];
            af[3] = Ps[mm+lr+8][kk+lc+4];
            #pragma unroll
            for (int j = 0; j < 8; j++) {
                uint32_t bf[2];
                bf[0] = Vs[kk+lc  ][8*j+lr];
                bf[1] = Vs[kk+lc+4][8*j+lr];
                mma_tf32(o[j], af, bf);
            }
        }
        __syncthreads();
    }

    // ---- epilogue
    const float i0 = 1.0f / l0;
    const float i1 = 1.0f / l1;
    float* ob = attn_out + (long)b*L_*D_ + h*HD_;
    #pragma unroll
    for (int j = 0; j < 8; j++) {
        const int nn = 8*j + 2*lc;
        *(float2*)(ob + (long)r0g*D_ + nn) = make_float2(o[j][0]*i0, o[j][1]*i0);
        *(float2*)(ob + (long)r1g*D_ + nn) = make_float2(o[j][2]*i1, o[j][3]*i1);
    }
}

// ---------------------------------------------------------------------------
// Launch
// ---------------------------------------------------------------------------
extern "C" void kernel_launch(void* const* d_in, const int* in_sizes, int n_in,
                              void* d_out, int out_size)
{
    const float* x     = (const float*)d_in[0];
    const int*   edges = (const int*)  d_in[1];
    const float* w_qkv = (const float*)d_in[2];
    const float* b_qkv = (const float*)d_in[3];
    const float* w_out = (const float*)d_in[4];
    const float* b_out = (const float*)d_in[5];
    float* out = (float*)d_out;
    const int E = in_sizes[1] / 2;

    float *qkv, *attn; unsigned* adj;
    cudaGetSymbolAddress((void**)&qkv,  g_qkv);
    cudaGetSymbolAddress((void**)&attn, g_attn);
    cudaGetSymbolAddress((void**)&adj,  g_adj);

    static int smem_set = 0;
    if (!smem_set) {
        cudaFuncSetAttribute(flash_kernel,
                             cudaFuncAttributeMaxDynamicSharedMemorySize, FL_SMEM);
        cudaFuncSetAttribute(gemm_tc_pipe<128,128,32,2,4>,
                             cudaFuncAttributeMaxDynamicSharedMemorySize, GEMM_SMEM);
        smem_set = 1;
    }

    // 1) adjacency bitmask
    zero_adj_kernel<<<(L_*ADJW + 255) / 256, 256>>>(adj);
    build_adj_kernel<<<(E + 255) / 256, 256>>>(adj, edges, E);

    // 2) QKV projection: [4096,3072] = X[4096,1024] @ Wqkv[3072,1024]^T + b
    {
        dim3 g(D3_/128, (B_*L_)/128);
        gemm_tc_pipe<128,128,32,2,4><<<g, 256, GEMM_SMEM>>>(
            x, w_qkv, b_qkv, qkv, D_, D_, D3_, D_);
    }

    // 3) fused masked attention (scores never materialized)
    {
        dim3 g(L_/128, B_*H_);
        flash_kernel<<<g, 256, FL_SMEM>>>(qkv, adj, attn);
    }

    // 4) out projection: [4096,1024] = attn[4096,1024] @ Wout[1024,1024]^T + b
    {
        dim3 g(D_/128, (B_*L_)/128);
        gemm_tc_pipe<128,128,32,2,4><<<g, 256, GEMM_SMEM>>>(
            attn, w_out, b_out, out, D_, D_, D_, D_);
    }
}

// round 9
// speedup vs baseline: 1.2430x; 1.2430x over previous
#include <cuda_runtime.h>
#include <math.h>
#include <stdint.h>

#define B_ 4
#define L_ 1024
#define D_ 1024
#define H_ 16
#define HD_ 64
#define D3_ 3072
#define ADJW (L_/32)

// Scratch (device globals: allocation-free rule)
__device__ float g_qkv[B_*L_*D3_];            // 48 MB   [B,L,3D]
__device__ float g_attn[B_*L_*D_];            // 16 MB   [B,L,D]
__device__ unsigned g_adj[L_*ADJW];           // 128 KB  bitmask

// ---------------------------------------------------------------------------
// Helpers
// ---------------------------------------------------------------------------
__device__ __forceinline__ uint32_t f2tf32(float x) {
    uint32_t r;
    asm("cvt.rna.tf32.f32 %0, %1;" : "=r"(r) : "f"(x));
    return r;
}

__device__ __forceinline__ void mma_tf32(float* d, const uint32_t* a, const uint32_t* b) {
    asm volatile(
        "mma.sync.aligned.m16n8k8.row.col.f32.tf32.tf32.f32 "
        "{%0,%1,%2,%3}, {%4,%5,%6,%7}, {%8,%9}, {%0,%1,%2,%3};"
        : "+f"(d[0]), "+f"(d[1]), "+f"(d[2]), "+f"(d[3])
        : "r"(a[0]), "r"(a[1]), "r"(a[2]), "r"(a[3]),
          "r"(b[0]), "r"(b[1]));
}

__device__ __forceinline__ void cp_async16(void* dst, const void* src) {
    uint32_t d = (uint32_t)__cvta_generic_to_shared(dst);
    asm volatile("cp.async.cg.shared.global [%0], [%1], 16;\n" :: "r"(d), "l"(src));
}
__device__ __forceinline__ void cp_commit() {
    asm volatile("cp.async.commit_group;\n");
}
template<int N>
__device__ __forceinline__ void cp_wait() {
    asm volatile("cp.async.wait_group %0;\n" :: "n"(N));
}

// ---------------------------------------------------------------------------
// Adjacency build
// ---------------------------------------------------------------------------
__global__ void zero_adj_kernel(unsigned* adj) {
    int i = blockIdx.x * blockDim.x + threadIdx.x;
    if (i < L_*ADJW) adj[i] = 0u;
}

__global__ void build_adj_kernel(unsigned* adj, const int* __restrict__ edges, int E) {
    int e = blockIdx.x * blockDim.x + threadIdx.x;
    if (e < E) {
        int i = edges[2*e], j = edges[2*e+1];
        atomicOr(&adj[i*ADJW + (j >> 5)], 1u << (j & 31));
        atomicOr(&adj[j*ADJW + (i >> 5)], 1u << (i & 31));
    }
}

// ---------------------------------------------------------------------------
// Tensor-core tf32 GEMM with register-prefetch double buffering.
//   C[m,n] = sum_k A[m*lda+k] * B[n*ldb+k] + bias[n]     (both K-major)
// Same smem layout / compute body as the validated R6 kernel (cvt at STS,
// PAD=8 -> conflict-free fragment LDS). The next tile's LDGs are issued
// into registers before the compute phase, hiding DRAM latency behind MMAs.
// ---------------------------------------------------------------------------
template<int BM, int BN, int BK, int WM, int WN>
__global__ void __launch_bounds__(WM*WN*32, 2)
gemm_tc(const float* __restrict__ A, const float* __restrict__ Bm,
        const float* __restrict__ bias, float* __restrict__ C,
        int lda, int ldb, int ldc, int K)
{
    constexpr int NT  = WM*WN*32;
    constexpr int WTM = BM/WM;      // 64
    constexpr int WTN = BN/WN;      // 32
    constexpr int MI  = WTM/16;     // 4
    constexpr int NI  = WTN/8;      // 4
    constexpr int PAD = 8;
    constexpr int CP  = BK/4;       // 4
    constexpr int RPP = NT / CP;    // 64
    constexpr int PA  = BM/RPP;     // 2
    constexpr int PB  = BN/RPP;     // 2

    __shared__ uint32_t As[BK][BM+PAD];
    __shared__ uint32_t Bs[BK][BN+PAD];

    const int tid  = threadIdx.x;
    const int wid  = tid >> 5;
    const int lane = tid & 31;
    const int wm   = wid / WN;
    const int wn   = wid % WN;
    const int m0   = blockIdx.y * BM;
    const int n0   = blockIdx.x * BN;
    const int lr   = lane >> 2;
    const int lc   = lane & 3;

    const int lrow = tid / CP;          // 0..63
    const int lcol = (tid % CP) * 4;

    float4 pa[PA], pb[PB];
    auto ldg_tile = [&](int k0) {
        #pragma unroll
        for (int p = 0; p < PA; p++)
            pa[p] = *(const float4*)(A + (long)(m0 + lrow + p*RPP) * lda + k0 + lcol);
        #pragma unroll
        for (int p = 0; p < PB; p++)
            pb[p] = *(const float4*)(Bm + (long)(n0 + lrow + p*RPP) * ldb + k0 + lcol);
    };
    auto sts_tile = [&]() {
        #pragma unroll
        for (int p = 0; p < PA; p++) {
            const int r = lrow + p*RPP;
            As[lcol+0][r] = f2tf32(pa[p].x); As[lcol+1][r] = f2tf32(pa[p].y);
            As[lcol+2][r] = f2tf32(pa[p].z); As[lcol+3][r] = f2tf32(pa[p].w);
        }
        #pragma unroll
        for (int p = 0; p < PB; p++) {
            const int r = lrow + p*RPP;
            Bs[lcol+0][r] = f2tf32(pb[p].x); Bs[lcol+1][r] = f2tf32(pb[p].y);
            Bs[lcol+2][r] = f2tf32(pb[p].z); Bs[lcol+3][r] = f2tf32(pb[p].w);
        }
    };

    float acc[MI][NI][4];
    #pragma unroll
    for (int i = 0; i < MI; i++)
        #pragma unroll
        for (int j = 0; j < NI; j++)
            #pragma unroll
            for (int r = 0; r < 4; r++) acc[i][j][r] = 0.0f;

    const int NKI = K / BK;
    ldg_tile(0);

    for (int ki = 0; ki < NKI; ki++) {
        sts_tile();
        __syncthreads();
        if (ki + 1 < NKI) ldg_tile((ki + 1) * BK);   // overlap with compute

        #pragma unroll
        for (int kk = 0; kk < BK; kk += 8) {
            uint32_t af[MI][4], bf[NI][2];
            #pragma unroll
            for (int i = 0; i < MI; i++) {
                const int mmx = wm*WTM + i*16;
                af[i][0] = As[kk+lc  ][mmx+lr  ];
                af[i][1] = As[kk+lc  ][mmx+lr+8];
                af[i][2] = As[kk+lc+4][mmx+lr  ];
                af[i][3] = As[kk+lc+4][mmx+lr+8];
            }
            #pragma unroll
            for (int j = 0; j < NI; j++) {
                const int nn = wn*WTN + j*8;
                bf[j][0] = Bs[kk+lc  ][nn+lr];
                bf[j][1] = Bs[kk+lc+4][nn+lr];
            }
            #pragma unroll
            for (int i = 0; i < MI; i++)
                #pragma unroll
                for (int j = 0; j < NI; j++)
                    mma_tf32(acc[i][j], af[i], bf[j]);
        }
        __syncthreads();
    }

    #pragma unroll
    for (int i = 0; i < MI; i++) {
        #pragma unroll
        for (int j = 0; j < NI; j++) {
            const int mmx = m0 + wm*WTM + i*16 + lr;
            const int nn  = n0 + wn*WTN + j*8 + lc*2;
            float2 v0 = make_float2(acc[i][j][0], acc[i][j][1]);
            float2 v1 = make_float2(acc[i][j][2], acc[i][j][3]);
            const float2 bb = *(const float2*)(bias + nn);
            v0.x += bb.x; v0.y += bb.y;
            v1.x += bb.x; v1.y += bb.y;
            *(float2*)(C + (long)mmx * ldc + nn)     = v0;
            *(float2*)(C + (long)(mmx+8) * ldc + nn) = v1;
        }
    }
}

// ---------------------------------------------------------------------------
// Fused flash attention with graph mask.
// vs R6: (a) P stays in registers; C-frag -> A-frag via warp shuffles
//        (P(lr, 8g+lc) lives in lane (lane&28)|(lc>>1), reg lc&1; +4 cols = src|2)
//        (b) K/V double-buffered via cp.async, raw fp32 fed to tf32 MMA
//        (HW uses top 19 bits). Q/P still rna-converted. One barrier/tile.
// Smem: Q 128x68 + 2x K 64x68 + 2x V 64x72 = 106.5 KB -> 2 CTAs/SM.
// ---------------------------------------------------------------------------
#define FL_SMEM ((128*68 + 2*64*68 + 2*64*72) * 4)

__global__ void __launch_bounds__(256, 2)
flash_kernel(const float* __restrict__ qkv, const unsigned* __restrict__ adj,
             float* __restrict__ attn_out)
{
    extern __shared__ uint32_t smf[];
    uint32_t (*Qs)[68]     = (uint32_t(*)[68])(smf);                    // [qrow][hd]
    uint32_t (*Ks)[64][68] = (uint32_t(*)[64][68])(smf + 128*68);       // [st][key][hd]
    uint32_t (*Vs)[64][72] = (uint32_t(*)[64][72])(smf + 128*68 + 2*64*68);

    const int q0 = blockIdx.x * 128;
    const int b  = blockIdx.y / H_;
    const int h  = blockIdx.y % H_;

    const int tid  = threadIdx.x;
    const int wid  = tid >> 5;
    const int lane = tid & 31;
    const int lr   = lane >> 2;
    const int lc   = lane & 3;
    const int mm   = wid * 16;

    const float* qb = qkv + (long)b*L_*D3_ + h*HD_;
    const float* kb = qb + D_;
    const float* vb = qb + 2*D_;

    // cp.async loader for one K/V stage (chunk-linear: coalesced 16B)
    auto load_kv = [&](int st, int kbase) {
        #pragma unroll
        for (int p = 0; p < 4; p++) {
            const int c = tid + 256*p;
            const int r = c >> 4;
            const int w = (c & 15) * 4;
            const long row = (long)(kbase + r) * D3_;
            cp_async16(&Ks[st][r][w], kb + row + w);
            cp_async16(&Vs[st][r][w], vb + row + w);
        }
        cp_commit();
    };

    load_kv(0, 0);

    // ---- Q tile (pre-scaled by 1/8, rna tf32)
    {
        const int r  = tid >> 4;
        const int c4 = (tid & 15) * 4;
        #pragma unroll
        for (int p = 0; p < 8; p++) {
            const float4 v = *(const float4*)(qb + (long)(q0 + r + p*16)*D3_ + c4);
            Qs[r+p*16][c4+0] = f2tf32(v.x * 0.125f);
            Qs[r+p*16][c4+1] = f2tf32(v.y * 0.125f);
            Qs[r+p*16][c4+2] = f2tf32(v.z * 0.125f);
            Qs[r+p*16][c4+3] = f2tf32(v.w * 0.125f);
        }
    }

    const int r0g = q0 + mm + lr;
    const int r1g = r0g + 8;
    const unsigned* adj0 = adj + (long)r0g * ADJW;
    const unsigned* adj1 = adj + (long)r1g * ADJW;

    float o[8][4];
    #pragma unroll
    for (int j = 0; j < 8; j++)
        #pragma unroll
        for (int r = 0; r < 4; r++) o[j][r] = 0.0f;
    float m0 = -INFINITY, m1 = -INFINITY, l0 = 0.0f, l1 = 0.0f;

    for (int kt = 0; kt < 16; kt++) {
        cp_wait<0>();
        __syncthreads();                 // tile kt visible; all warps done with kt-1
        if (kt + 1 < 16) load_kv((kt + 1) & 1, (kt + 1) * 64);
        const int st = kt & 1;

        // ---- S = (Q/8) K^T : warp tile 16 x 64 (K raw fp32 -> truncated tf32)
        float sc[8][4];
        #pragma unroll
        for (int j = 0; j < 8; j++)
            #pragma unroll
            for (int r = 0; r < 4; r++) sc[j][r] = 0.0f;

        #pragma unroll
        for (int kk = 0; kk < 64; kk += 8) {
            uint32_t af[4];
            af[0] = Qs[mm+lr  ][kk+lc  ];
            af[1] = Qs[mm+lr+8][kk+lc  ];
            af[2] = Qs[mm+lr  ][kk+lc+4];
            af[3] = Qs[mm+lr+8][kk+lc+4];
            #pragma unroll
            for (int j = 0; j < 8; j++) {
                uint32_t bf[2];
                bf[0] = Ks[st][8*j+lr][kk+lc  ];
                bf[1] = Ks[st][8*j+lr][kk+lc+4];
                mma_tf32(sc[j], af, bf);
            }
        }

        // ---- mask + online softmax (rows lr / lr+8)
        const unsigned wA0 = adj0[2*kt], wA1 = adj0[2*kt+1];
        const unsigned wB0 = adj1[2*kt], wB1 = adj1[2*kt+1];
        float tm0 = -INFINITY, tm1 = -INFINITY;
        unsigned mk = 0;
        #pragma unroll
        for (int j = 0; j < 8; j++) {
            const int cbit = (8*j + 2*lc) & 31;
            const unsigned wa = (j < 4) ? wA0 : wA1;
            const unsigned wb = (j < 4) ? wB0 : wB1;
            const unsigned f00 = (wa >> cbit) & 1u;
            const unsigned f01 = (wa >> (cbit+1)) & 1u;
            const unsigned f10 = (wb >> cbit) & 1u;
            const unsigned f11 = (wb >> (cbit+1)) & 1u;
            mk |= (f00 | (f01 << 1) | (f10 << 2) | (f11 << 3)) << (4*j);
            if (!f00) tm0 = fmaxf(tm0, sc[j][0]);
            if (!f01) tm0 = fmaxf(tm0, sc[j][1]);
            if (!f10) tm1 = fmaxf(tm1, sc[j][2]);
            if (!f11) tm1 = fmaxf(tm1, sc[j][3]);
        }
        tm0 = fmaxf(tm0, __shfl_xor_sync(0xFFFFFFFFu, tm0, 1));
        tm0 = fmaxf(tm0, __shfl_xor_sync(0xFFFFFFFFu, tm0, 2));
        tm1 = fmaxf(tm1, __shfl_xor_sync(0xFFFFFFFFu, tm1, 1));
        tm1 = fmaxf(tm1, __shfl_xor_sync(0xFFFFFFFFu, tm1, 2));

        const float mn0 = fmaxf(m0, tm0);
        const float mn1 = fmaxf(m1, tm1);
        const float a0 = (m0 == -INFINITY) ? 0.0f : __expf(m0 - mn0);
        const float a1 = (m1 == -INFINITY) ? 0.0f : __expf(m1 - mn1);
        m0 = mn0; m1 = mn1;

        float rs0 = 0.0f, rs1 = 0.0f;
        #pragma unroll
        for (int j = 0; j < 8; j++) {
            const unsigned mj = mk >> (4*j);
            const float p0 = (mj & 1u) ? 0.0f : __expf(sc[j][0] - mn0);
            const float p1 = (mj & 2u) ? 0.0f : __expf(sc[j][1] - mn0);
            const float p2 = (mj & 4u) ? 0.0f : __expf(sc[j][2] - mn1);
            const float p3 = (mj & 8u) ? 0.0f : __expf(sc[j][3] - mn1);
            rs0 += p0 + p1;
            rs1 += p2 + p3;
            sc[j][0] = p0; sc[j][1] = p1; sc[j][2] = p2; sc[j][3] = p3;
        }
        rs0 += __shfl_xor_sync(0xFFFFFFFFu, rs0, 1);
        rs0 += __shfl_xor_sync(0xFFFFFFFFu, rs0, 2);
        rs1 += __shfl_xor_sync(0xFFFFFFFFu, rs1, 1);
        rs1 += __shfl_xor_sync(0xFFFFFFFFu, rs1, 2);
        l0 = a0*l0 + rs0;
        l1 = a1*l1 + rs1;

        #pragma unroll
        for (int j = 0; j < 8; j++) {
            o[j][0] *= a0; o[j][1] *= a0;
            o[j][2] *= a1; o[j][3] *= a1;
        }

        // ---- O += P V : C-frag -> A-frag via shuffles, V raw fp32
        const int src  = (lane & 28) | (lc >> 1);
        const int src2 = src | 2;
        const bool odd = (lc & 1);
        #pragma unroll
        for (int g = 0; g < 8; g++) {
            const float s00 = __shfl_sync(0xFFFFFFFFu, sc[g][0], src);
            const float s01 = __shfl_sync(0xFFFFFFFFu, sc[g][1], src);
            const float s10 = __shfl_sync(0xFFFFFFFFu, sc[g][2], src);
            const float s11 = __shfl_sync(0xFFFFFFFFu, sc[g][3], src);
            const float t00 = __shfl_sync(0xFFFFFFFFu, sc[g][0], src2);
            const float t01 = __shfl_sync(0xFFFFFFFFu, sc[g][1], src2);
            const float t10 = __shfl_sync(0xFFFFFFFFu, sc[g][2], src2);
            const float t11 = __shfl_sync(0xFFFFFFFFu, sc[g][3], src2);
            uint32_t af[4];
            af[0] = f2tf32(odd ? s01 : s00);
            af[1] = f2tf32(odd ? s11 : s10);
            af[2] = f2tf32(odd ? t01 : t00);
            af[3] = f2tf32(odd ? t11 : t10);
            const int kk = 8*g;
            #pragma unroll
            for (int j = 0; j < 8; j++) {
                uint32_t bf[2];
                bf[0] = Vs[st][kk+lc  ][8*j+lr];
                bf[1] = Vs[st][kk+lc+4][8*j+lr];
                mma_tf32(o[j], af, bf);
            }
        }
    }

    // ---- epilogue
    const float i0 = 1.0f / l0;
    const float i1 = 1.0f / l1;
    float* ob = attn_out + (long)b*L_*D_ + h*HD_;
    #pragma unroll
    for (int j = 0; j < 8; j++) {
        const int nn = 8*j + 2*lc;
        *(float2*)(ob + (long)r0g*D_ + nn) = make_float2(o[j][0]*i0, o[j][1]*i0);
        *(float2*)(ob + (long)r1g*D_ + nn) = make_float2(o[j][2]*i1, o[j][3]*i1);
    }
}

// ---------------------------------------------------------------------------
// Launch
// ---------------------------------------------------------------------------
extern "C" void kernel_launch(void* const* d_in, const int* in_sizes, int n_in,
                              void* d_out, int out_size)
{
    const float* x     = (const float*)d_in[0];
    const int*   edges = (const int*)  d_in[1];
    const float* w_qkv = (const float*)d_in[2];
    const float* b_qkv = (const float*)d_in[3];
    const float* w_out = (const float*)d_in[4];
    const float* b_out = (const float*)d_in[5];
    float* out = (float*)d_out;
    const int E = in_sizes[1] / 2;

    float *qkv, *attn; unsigned* adj;
    cudaGetSymbolAddress((void**)&qkv,  g_qkv);
    cudaGetSymbolAddress((void**)&attn, g_attn);
    cudaGetSymbolAddress((void**)&adj,  g_adj);

    static int smem_set = 0;
    if (!smem_set) {
        cudaFuncSetAttribute(flash_kernel,
                             cudaFuncAttributeMaxDynamicSharedMemorySize, FL_SMEM);
        smem_set = 1;
    }

    // 1) adjacency bitmask
    zero_adj_kernel<<<(L_*ADJW + 255) / 256, 256>>>(adj);
    build_adj_kernel<<<(E + 255) / 256, 256>>>(adj, edges, E);

    // 2) QKV projection: [4096,3072] = X[4096,1024] @ Wqkv[3072,1024]^T + b
    {
        dim3 g(D3_/128, (B_*L_)/128);
        gemm_tc<128,128,16,2,4><<<g, 256>>>(
            x, w_qkv, b_qkv, qkv, D_, D_, D3_, D_);
    }

    // 3) fused masked attention (scores never materialized)
    {
        dim3 g(L_/128, B_*H_);
        flash_kernel<<<g, 256, FL_SMEM>>>(qkv, adj, attn);
    }

    // 4) out projection: [4096,1024] = attn[4096,1024] @ Wout[1024,1024]^T + b
    {
        dim3 g(D_/128, (B_*L_)/128);
        gemm_tc<128,128,16,2,4><<<g, 256>>>(
            attn, w_out, b_out, out, D_, D_, D_, D_);
    }
}

// round 14
// speedup vs baseline: 1.5281x; 1.2294x over previous
#include <cuda_runtime.h>
#include <math.h>
#include <stdint.h>

#define B_ 4
#define L_ 1024
#define D_ 1024
#define H_ 16
#define HD_ 64
#define D3_ 3072
#define ADJW (L_/32)

// Scratch (device globals: allocation-free rule)
__device__ float g_qkv[B_*L_*D3_];            // 48 MB   [B,L,3D]
__device__ float g_attn[B_*L_*D_];            // 16 MB   [B,L,D]
__device__ unsigned g_adj[L_*ADJW];           // 128 KB  bitmask

// ---------------------------------------------------------------------------
// Helpers
// ---------------------------------------------------------------------------
__device__ __forceinline__ uint32_t f2tf32(float x) {
    uint32_t r;
    asm("cvt.rna.tf32.f32 %0, %1;" : "=r"(r) : "f"(x));
    return r;
}

__device__ __forceinline__ void mma_tf32(float* d, const uint32_t* a, const uint32_t* b) {
    asm volatile(
        "mma.sync.aligned.m16n8k8.row.col.f32.tf32.tf32.f32 "
        "{%0,%1,%2,%3}, {%4,%5,%6,%7}, {%8,%9}, {%0,%1,%2,%3};"
        : "+f"(d[0]), "+f"(d[1]), "+f"(d[2]), "+f"(d[3])
        : "r"(a[0]), "r"(a[1]), "r"(a[2]), "r"(a[3]),
          "r"(b[0]), "r"(b[1]));
}

// ldmatrix x4: four 8x8 b16 tiles (= four 8x4 b32 tiles)
__device__ __forceinline__ void ldsm_x4(uint32_t* r, uint32_t saddr) {
    asm volatile("ldmatrix.sync.aligned.m8n8.x4.shared.b16 {%0,%1,%2,%3}, [%4];"
        : "=r"(r[0]), "=r"(r[1]), "=r"(r[2]), "=r"(r[3]) : "r"(saddr));
}

__device__ __forceinline__ void cp_async16(void* dst, const void* src) {
    uint32_t d = (uint32_t)__cvta_generic_to_shared(dst);
    asm volatile("cp.async.cg.shared.global [%0], [%1], 16;\n" :: "r"(d), "l"(src));
}
__device__ __forceinline__ void cp_commit() {
    asm volatile("cp.async.commit_group;\n");
}
template<int N>
__device__ __forceinline__ void cp_wait() {
    asm volatile("cp.async.wait_group %0;\n" :: "n"(N));
}

// ---------------------------------------------------------------------------
// Adjacency build
// ---------------------------------------------------------------------------
__global__ void zero_adj_kernel(unsigned* adj) {
    int i = blockIdx.x * blockDim.x + threadIdx.x;
    if (i < L_*ADJW) adj[i] = 0u;
}

__global__ void build_adj_kernel(unsigned* adj, const int* __restrict__ edges, int E) {
    int e = blockIdx.x * blockDim.x + threadIdx.x;
    if (e < E) {
        int i = edges[2*e], j = edges[2*e+1];
        atomicOr(&adj[i*ADJW + (j >> 5)], 1u << (j & 31));
        atomicOr(&adj[j*ADJW + (i >> 5)], 1u << (i & 31));
    }
}

// ---------------------------------------------------------------------------
// Tensor-core tf32 GEMM: register-prefetch double buffering + ldmatrix frags.
//   C[m,n] = sum_k A[m*lda+k] * B[n*ldb+k] + bias[n]     (both K-major)
// Tiles stored [m][k] / [n][k] row-major, stride 20 words (==20 mod 32 ->
// ldmatrix 8-row phases hit banks {0,20,8,28,16,4,24,12}+{0..3}: conflict-free).
// A-frag: ldmatrix.x4 @ row m0+(lane&15), col kk+((lane>>4)<<2) -> a0..a3.
// B-frag: same addressing on [n][k] covers TWO n8-tiles per x4.
// cvt.rna at STS (once per element), identical numerics to R9.
// ---------------------------------------------------------------------------
template<int BM, int BN, int BK, int WM, int WN>
__global__ void __launch_bounds__(WM*WN*32, 2)
gemm_tc(const float* __restrict__ A, const float* __restrict__ Bm,
        const float* __restrict__ bias, float* __restrict__ C,
        int lda, int ldb, int ldc, int K)
{
    constexpr int NT  = WM*WN*32;
    constexpr int WTM = BM/WM;      // 64
    constexpr int WTN = BN/WN;      // 32
    constexpr int MI  = WTM/16;     // 4
    constexpr int NI  = WTN/8;      // 4
    constexpr int STR = BK + 4;     // 20
    constexpr int CP  = BK/4;       // 4
    constexpr int RPP = NT / CP;    // 64
    constexpr int PA  = BM/RPP;     // 2
    constexpr int PB  = BN/RPP;     // 2

    __shared__ uint32_t As[BM][STR];
    __shared__ uint32_t Bs[BN][STR];

    const int tid  = threadIdx.x;
    const int wid  = tid >> 5;
    const int lane = tid & 31;
    const int wm   = wid / WN;
    const int wn   = wid % WN;
    const int m0   = blockIdx.y * BM;
    const int n0   = blockIdx.x * BN;
    const int lr   = lane >> 2;
    const int lc   = lane & 3;

    const uint32_t as_base = (uint32_t)__cvta_generic_to_shared(&As[0][0]);
    const uint32_t bs_base = (uint32_t)__cvta_generic_to_shared(&Bs[0][0]);
    const int lsel = (lane & 15);                // ldmatrix row select
    const int ksel = (lane >> 4) << 2;           // ldmatrix col select (0 or 4)

    const int lrow = tid / CP;          // 0..63
    const int lcol = (tid % CP) * 4;

    float4 pa[PA], pb[PB];
    auto ldg_tile = [&](int k0) {
        #pragma unroll
        for (int p = 0; p < PA; p++)
            pa[p] = *(const float4*)(A + (long)(m0 + lrow + p*RPP) * lda + k0 + lcol);
        #pragma unroll
        for (int p = 0; p < PB; p++)
            pb[p] = *(const float4*)(Bm + (long)(n0 + lrow + p*RPP) * ldb + k0 + lcol);
    };
    auto sts_tile = [&]() {
        #pragma unroll
        for (int p = 0; p < PA; p++) {
            const int r = lrow + p*RPP;
            As[r][lcol+0] = f2tf32(pa[p].x); As[r][lcol+1] = f2tf32(pa[p].y);
            As[r][lcol+2] = f2tf32(pa[p].z); As[r][lcol+3] = f2tf32(pa[p].w);
        }
        #pragma unroll
        for (int p = 0; p < PB; p++) {
            const int r = lrow + p*RPP;
            Bs[r][lcol+0] = f2tf32(pb[p].x); Bs[r][lcol+1] = f2tf32(pb[p].y);
            Bs[r][lcol+2] = f2tf32(pb[p].z); Bs[r][lcol+3] = f2tf32(pb[p].w);
        }
    };

    float acc[MI][NI][4];
    #pragma unroll
    for (int i = 0; i < MI; i++)
        #pragma unroll
        for (int j = 0; j < NI; j++)
            #pragma unroll
            for (int r = 0; r < 4; r++) acc[i][j][r] = 0.0f;

    const int NKI = K / BK;
    ldg_tile(0);

    for (int ki = 0; ki < NKI; ki++) {
        sts_tile();
        __syncthreads();
        if (ki + 1 < NKI) ldg_tile((ki + 1) * BK);   // overlap with compute

        #pragma unroll
        for (int kk = 0; kk < BK; kk += 8) {
            uint32_t af[MI][4], bf[NI][2];
            #pragma unroll
            for (int i = 0; i < MI; i++) {
                const int mmx = wm*WTM + i*16 + lsel;
                ldsm_x4(af[i], as_base + (uint32_t)((mmx*STR + kk + ksel) << 2));
            }
            #pragma unroll
            for (int jj = 0; jj < NI/2; jj++) {
                const int nn = wn*WTN + jj*16 + lsel;
                uint32_t t[4];
                ldsm_x4(t, bs_base + (uint32_t)((nn*STR + kk + ksel) << 2));
                bf[2*jj  ][0] = t[0]; bf[2*jj+1][0] = t[1];
                bf[2*jj  ][1] = t[2]; bf[2*jj+1][1] = t[3];
            }
            #pragma unroll
            for (int i = 0; i < MI; i++)
                #pragma unroll
                for (int j = 0; j < NI; j++)
                    mma_tf32(acc[i][j], af[i], bf[j]);
        }
        __syncthreads();
    }

    #pragma unroll
    for (int i = 0; i < MI; i++) {
        #pragma unroll
        for (int j = 0; j < NI; j++) {
            const int mmx = m0 + wm*WTM + i*16 + lr;
            const int nn  = n0 + wn*WTN + j*8 + lc*2;
            float2 v0 = make_float2(acc[i][j][0], acc[i][j][1]);
            float2 v1 = make_float2(acc[i][j][2], acc[i][j][3]);
            const float2 bb = *(const float2*)(bias + nn);
            v0.x += bb.x; v0.y += bb.y;
            v1.x += bb.x; v1.y += bb.y;
            *(float2*)(C + (long)mmx * ldc + nn)     = v0;
            *(float2*)(C + (long)(mmx+8) * ldc + nn) = v1;
        }
    }
}

// ---------------------------------------------------------------------------
// Fused flash attention with graph mask.
// vs R9: Q/K fragment loads in the S mainloop now use ldmatrix
// (strides 68 == 4 mod 32 -> phase banks i*4: conflict-free).
// P-register shuffles and V scalar loads unchanged.
// ---------------------------------------------------------------------------
#define FL_SMEM ((128*68 + 2*64*68 + 2*64*72) * 4)

__global__ void __launch_bounds__(256, 2)
flash_kernel(const float* __restrict__ qkv, const unsigned* __restrict__ adj,
             float* __restrict__ attn_out)
{
    extern __shared__ uint32_t smf[];
    uint32_t (*Qs)[68]     = (uint32_t(*)[68])(smf);
    uint32_t (*Ks)[64][68] = (uint32_t(*)[64][68])(smf + 128*68);
    uint32_t (*Vs)[64][72] = (uint32_t(*)[64][72])(smf + 128*68 + 2*64*68);

    const int q0 = blockIdx.x * 128;
    const int b  = blockIdx.y / H_;
    const int h  = blockIdx.y % H_;

    const int tid  = threadIdx.x;
    const int wid  = tid >> 5;
    const int lane = tid & 31;
    const int lr   = lane >> 2;
    const int lc   = lane & 3;
    const int mm   = wid * 16;
    const int lsel = (lane & 15);
    const int ksel = (lane >> 4) << 2;

    const uint32_t qs_base = (uint32_t)__cvta_generic_to_shared(&Qs[0][0]);
    const uint32_t ks_base = (uint32_t)__cvta_generic_to_shared(&Ks[0][0][0]);

    const float* qb = qkv + (long)b*L_*D3_ + h*HD_;
    const float* kb = qb + D_;
    const float* vb = qb + 2*D_;

    auto load_kv = [&](int st, int kbase) {
        #pragma unroll
        for (int p = 0; p < 4; p++) {
            const int c = tid + 256*p;
            const int r = c >> 4;
            const int w = (c & 15) * 4;
            const long row = (long)(kbase + r) * D3_;
            cp_async16(&Ks[st][r][w], kb + row + w);
            cp_async16(&Vs[st][r][w], vb + row + w);
        }
        cp_commit();
    };

    load_kv(0, 0);

    {
        const int r  = tid >> 4;
        const int c4 = (tid & 15) * 4;
        #pragma unroll
        for (int p = 0; p < 8; p++) {
            const float4 v = *(const float4*)(qb + (long)(q0 + r + p*16)*D3_ + c4);
            Qs[r+p*16][c4+0] = f2tf32(v.x * 0.125f);
            Qs[r+p*16][c4+1] = f2tf32(v.y * 0.125f);
            Qs[r+p*16][c4+2] = f2tf32(v.z * 0.125f);
            Qs[r+p*16][c4+3] = f2tf32(v.w * 0.125f);
        }
    }

    const int r0g = q0 + mm + lr;
    const int r1g = r0g + 8;
    const unsigned* adj0 = adj + (long)r0g * ADJW;
    const unsigned* adj1 = adj + (long)r1g * ADJW;

    float o[8][4];
    #pragma unroll
    for (int j = 0; j < 8; j++)
        #pragma unroll
        for (int r = 0; r < 4; r++) o[j][r] = 0.0f;
    float m0 = -INFINITY, m1 = -INFINITY, l0 = 0.0f, l1 = 0.0f;

    for (int kt = 0; kt < 16; kt++) {
        cp_wait<0>();
        __syncthreads();
        if (kt + 1 < 16) load_kv((kt + 1) & 1, (kt + 1) * 64);
        const int st = kt & 1;
        const uint32_t kst_base = ks_base + (uint32_t)(st * 64*68*4);

        // ---- S = (Q/8) K^T : warp tile 16 x 64, ldmatrix fragments
        float sc[8][4];
        #pragma unroll
        for (int j = 0; j < 8; j++)
            #pragma unroll
            for (int r = 0; r < 4; r++) sc[j][r] = 0.0f;

        #pragma unroll
        for (int kk = 0; kk < 64; kk += 8) {
            uint32_t af[4];
            ldsm_x4(af, qs_base + (uint32_t)(((mm + lsel)*68 + kk + ksel) << 2));
            #pragma unroll
            for (int jj = 0; jj < 4; jj++) {
                uint32_t t[4];
                ldsm_x4(t, kst_base + (uint32_t)(((16*jj + lsel)*68 + kk + ksel) << 2));
                uint32_t bf0[2] = {t[0], t[2]};
                uint32_t bf1[2] = {t[1], t[3]};
                mma_tf32(sc[2*jj  ], af, bf0);
                mma_tf32(sc[2*jj+1], af, bf1);
            }
        }

        // ---- mask + online softmax (rows lr / lr+8)
        const unsigned wA0 = adj0[2*kt], wA1 = adj0[2*kt+1];
        const unsigned wB0 = adj1[2*kt], wB1 = adj1[2*kt+1];
        float tm0 = -INFINITY, tm1 = -INFINITY;
        unsigned mk = 0;
        #pragma unroll
        for (int j = 0; j < 8; j++) {
            const int cbit = (8*j + 2*lc) & 31;
            const unsigned wa = (j < 4) ? wA0 : wA1;
            const unsigned wb = (j < 4) ? wB0 : wB1;
            const unsigned f00 = (wa >> cbit) & 1u;
            const unsigned f01 = (wa >> (cbit+1)) & 1u;
            const unsigned f10 = (wb >> cbit) & 1u;
            const unsigned f11 = (wb >> (cbit+1)) & 1u;
            mk |= (f00 | (f01 << 1) | (f10 << 2) | (f11 << 3)) << (4*j);
            if (!f00) tm0 = fmaxf(tm0, sc[j][0]);
            if (!f01) tm0 = fmaxf(tm0, sc[j][1]);
            if (!f10) tm1 = fmaxf(tm1, sc[j][2]);
            if (!f11) tm1 = fmaxf(tm1, sc[j][3]);
        }
        tm0 = fmaxf(tm0, __shfl_xor_sync(0xFFFFFFFFu, tm0, 1));
        tm0 = fmaxf(tm0, __shfl_xor_sync(0xFFFFFFFFu, tm0, 2));
        tm1 = fmaxf(tm1, __shfl_xor_sync(0xFFFFFFFFu, tm1, 1));
        tm1 = fmaxf(tm1, __shfl_xor_sync(0xFFFFFFFFu, tm1, 2));

        const float mn0 = fmaxf(m0, tm0);
        const float mn1 = fmaxf(m1, tm1);
        const float a0 = (m0 == -INFINITY) ? 0.0f : __expf(m0 - mn0);
        const float a1 = (m1 == -INFINITY) ? 0.0f : __expf(m1 - mn1);
        m0 = mn0; m1 = mn1;

        float rs0 = 0.0f, rs1 = 0.0f;
        #pragma unroll
        for (int j = 0; j < 8; j++) {
            const unsigned mj = mk >> (4*j);
            const float p0 = (mj & 1u) ? 0.0f : __expf(sc[j][0] - mn0);
            const float p1 = (mj & 2u) ? 0.0f : __expf(sc[j][1] - mn0);
            const float p2 = (mj & 4u) ? 0.0f : __expf(sc[j][2] - mn1);
            const float p3 = (mj & 8u) ? 0.0f : __expf(sc[j][3] - mn1);
            rs0 += p0 + p1;
            rs1 += p2 + p3;
            sc[j][0] = p0; sc[j][1] = p1; sc[j][2] = p2; sc[j][3] = p3;
        }
        rs0 += __shfl_xor_sync(0xFFFFFFFFu, rs0, 1);
        rs0 += __shfl_xor_sync(0xFFFFFFFFu, rs0, 2);
        rs1 += __shfl_xor_sync(0xFFFFFFFFu, rs1, 1);
        rs1 += __shfl_xor_sync(0xFFFFFFFFu, rs1, 2);
        l0 = a0*l0 + rs0;
        l1 = a1*l1 + rs1;

        #pragma unroll
        for (int j = 0; j < 8; j++) {
            o[j][0] *= a0; o[j][1] *= a0;
            o[j][2] *= a1; o[j][3] *= a1;
        }

        // ---- O += P V : C-frag -> A-frag via shuffles, V raw fp32
        const int src  = (lane & 28) | (lc >> 1);
        const int src2 = src | 2;
        const bool odd = (lc & 1);
        #pragma unroll
        for (int g = 0; g < 8; g++) {
            const float s00 = __shfl_sync(0xFFFFFFFFu, sc[g][0], src);
            const float s01 = __shfl_sync(0xFFFFFFFFu, sc[g][1], src);
            const float s10 = __shfl_sync(0xFFFFFFFFu, sc[g][2], src);
            const float s11 = __shfl_sync(0xFFFFFFFFu, sc[g][3], src);
            const float t00 = __shfl_sync(0xFFFFFFFFu, sc[g][0], src2);
            const float t01 = __shfl_sync(0xFFFFFFFFu, sc[g][1], src2);
            const float t10 = __shfl_sync(0xFFFFFFFFu, sc[g][2], src2);
            const float t11 = __shfl_sync(0xFFFFFFFFu, sc[g][3], src2);
            uint32_t af[4];
            af[0] = f2tf32(odd ? s01 : s00);
            af[1] = f2tf32(odd ? s11 : s10);
            af[2] = f2tf32(odd ? t01 : t00);
            af[3] = f2tf32(odd ? t11 : t10);
            const int kk = 8*g;
            #pragma unroll
            for (int j = 0; j < 8; j++) {
                uint32_t bf[2];
                bf[0] = Vs[st][kk+lc  ][8*j+lr];
                bf[1] = Vs[st][kk+lc+4][8*j+lr];
                mma_tf32(o[j], af, bf);
            }
        }
    }

    const float i0 = 1.0f / l0;
    const float i1 = 1.0f / l1;
    float* ob = attn_out + (long)b*L_*D_ + h*HD_;
    #pragma unroll
    for (int j = 0; j < 8; j++) {
        const int nn = 8*j + 2*lc;
        *(float2*)(ob + (long)r0g*D_ + nn) = make_float2(o[j][0]*i0, o[j][1]*i0);
        *(float2*)(ob + (long)r1g*D_ + nn) = make_float2(o[j][2]*i1, o[j][3]*i1);
    }
}

// ---------------------------------------------------------------------------
// Launch
// ---------------------------------------------------------------------------
extern "C" void kernel_launch(void* const* d_in, const int* in_sizes, int n_in,
                              void* d_out, int out_size)
{
    const float* x     = (const float*)d_in[0];
    const int*   edges = (const int*)  d_in[1];
    const float* w_qkv = (const float*)d_in[2];
    const float* b_qkv = (const float*)d_in[3];
    const float* w_out = (const float*)d_in[4];
    const float* b_out = (const float*)d_in[5];
    float* out = (float*)d_out;
    const int E = in_sizes[1] / 2;

    float *qkv, *attn; unsigned* adj;
    cudaGetSymbolAddress((void**)&qkv,  g_qkv);
    cudaGetSymbolAddress((void**)&attn, g_attn);
    cudaGetSymbolAddress((void**)&adj,  g_adj);

    static int smem_set = 0;
    if (!smem_set) {
        cudaFuncSetAttribute(flash_kernel,
                             cudaFuncAttributeMaxDynamicSharedMemorySize, FL_SMEM);
        smem_set = 1;
    }

    // 1) adjacency bitmask
    zero_adj_kernel<<<(L_*ADJW + 255) / 256, 256>>>(adj);
    build_adj_kernel<<<(E + 255) / 256, 256>>>(adj, edges, E);

    // 2) QKV projection: [4096,3072] = X[4096,1024] @ Wqkv[3072,1024]^T + b
    {
        dim3 g(D3_/128, (B_*L_)/128);
        gemm_tc<128,128,16,2,4><<<g, 256>>>(
            x, w_qkv, b_qkv, qkv, D_, D_, D3_, D_);
    }

    // 3) fused masked attention (scores never materialized)
    {
        dim3 g(L_/128, B_*H_);
        flash_kernel<<<g, 256, FL_SMEM>>>(qkv, adj, attn);
    }

    // 4) out projection: [4096,1024] = attn[4096,1024] @ Wout[1024,1024]^T + b
    {
        dim3 g(D_/128, (B_*L_)/128);
        gemm_tc<128,128,16,2,4><<<g, 256>>>(
            attn, w_out, b_out, out, D_, D_, D_, D_);
    }
}

// round 15
// speedup vs baseline: 1.6046x; 1.0501x over previous
#include <cuda_runtime.h>
#include <math.h>
#include <stdint.h>

#define B_ 4
#define L_ 1024
#define D_ 1024
#define H_ 16
#define HD_ 64
#define D3_ 3072
#define ADJW (L_/32)

// Scratch (device globals: allocation-free rule)
__device__ float g_qkv[B_*L_*D3_];            // 48 MB   [B,L,3D]
__device__ float g_attn[B_*L_*D_];            // 16 MB   [B,L,D]
__device__ unsigned g_adj[L_*ADJW];           // 128 KB  bitmask

// ---------------------------------------------------------------------------
// Helpers
// ---------------------------------------------------------------------------
__device__ __forceinline__ uint32_t f2tf32(float x) {
    uint32_t r;
    asm("cvt.rna.tf32.f32 %0, %1;" : "=r"(r) : "f"(x));
    return r;
}

__device__ __forceinline__ void mma_tf32(float* d, const uint32_t* a, const uint32_t* b) {
    asm volatile(
        "mma.sync.aligned.m16n8k8.row.col.f32.tf32.tf32.f32 "
        "{%0,%1,%2,%3}, {%4,%5,%6,%7}, {%8,%9}, {%0,%1,%2,%3};"
        : "+f"(d[0]), "+f"(d[1]), "+f"(d[2]), "+f"(d[3])
        : "r"(a[0]), "r"(a[1]), "r"(a[2]), "r"(a[3]),
          "r"(b[0]), "r"(b[1]));
}

// ldmatrix x4: four 8x8 b16 tiles (= four 8x4 b32 tiles)
__device__ __forceinline__ void ldsm_x4(uint32_t* r, uint32_t saddr) {
    asm volatile("ldmatrix.sync.aligned.m8n8.x4.shared.b16 {%0,%1,%2,%3}, [%4];"
        : "=r"(r[0]), "=r"(r[1]), "=r"(r[2]), "=r"(r[3]) : "r"(saddr));
}

__device__ __forceinline__ void cp_async16(void* dst, const void* src) {
    uint32_t d = (uint32_t)__cvta_generic_to_shared(dst);
    asm volatile("cp.async.cg.shared.global [%0], [%1], 16;\n" :: "r"(d), "l"(src));
}
__device__ __forceinline__ void cp_commit() {
    asm volatile("cp.async.commit_group;\n");
}
template<int N>
__device__ __forceinline__ void cp_wait() {
    asm volatile("cp.async.wait_group %0;\n" :: "n"(N));
}

// ---------------------------------------------------------------------------
// Adjacency build
// ---------------------------------------------------------------------------
__global__ void zero_adj_kernel(unsigned* adj) {
    int i = blockIdx.x * blockDim.x + threadIdx.x;
    if (i < L_*ADJW) adj[i] = 0u;
}

__global__ void build_adj_kernel(unsigned* adj, const int* __restrict__ edges, int E) {
    int e = blockIdx.x * blockDim.x + threadIdx.x;
    if (e < E) {
        int i = edges[2*e], j = edges[2*e+1];
        atomicOr(&adj[i*ADJW + (j >> 5)], 1u << (j & 31));
        atomicOr(&adj[j*ADJW + (i >> 5)], 1u << (i & 31));
    }
}

// ---------------------------------------------------------------------------
// Tensor-core tf32 GEMM: 2-stage smem double buffer (ONE sync per k-iter)
// + register-prefetch LDG + ldmatrix fragments.
//   C[m,n] = sum_k A[m*lda+k] * B[n*ldb+k] + bias[n]     (both K-major)
// Buffer (ki+1)&1 was last read in iter ki-1; the iter-(ki-1) sync makes the
// overwrite in iter ki safe without a second barrier.
// cvt.rna at STS (once per element) -> numerics identical to R14.
// ---------------------------------------------------------------------------
template<int BM, int BN, int BK, int WM, int WN>
__global__ void __launch_bounds__(WM*WN*32, 2)
gemm_tc(const float* __restrict__ A, const float* __restrict__ Bm,
        const float* __restrict__ bias, float* __restrict__ C,
        int lda, int ldb, int ldc, int K)
{
    constexpr int NT  = WM*WN*32;
    constexpr int WTM = BM/WM;      // 64
    constexpr int WTN = BN/WN;      // 32
    constexpr int MI  = WTM/16;     // 4
    constexpr int NI  = WTN/8;      // 4
    constexpr int STR = BK + 4;     // 20
    constexpr int CP  = BK/4;       // 4
    constexpr int RPP = NT / CP;    // 64
    constexpr int PA  = BM/RPP;     // 2
    constexpr int PB  = BN/RPP;     // 2

    __shared__ uint32_t As[2][BM][STR];
    __shared__ uint32_t Bs[2][BN][STR];

    const int tid  = threadIdx.x;
    const int wid  = tid >> 5;
    const int lane = tid & 31;
    const int wm   = wid / WN;
    const int wn   = wid % WN;
    const int m0   = blockIdx.y * BM;
    const int n0   = blockIdx.x * BN;
    const int lr   = lane >> 2;
    const int lc   = lane & 3;

    const int lsel = (lane & 15);
    const int ksel = (lane >> 4) << 2;

    const int lrow = tid / CP;          // 0..63
    const int lcol = (tid % CP) * 4;

    float4 pa[PA], pb[PB];
    auto ldg_tile = [&](int k0) {
        #pragma unroll
        for (int p = 0; p < PA; p++)
            pa[p] = *(const float4*)(A + (long)(m0 + lrow + p*RPP) * lda + k0 + lcol);
        #pragma unroll
        for (int p = 0; p < PB; p++)
            pb[p] = *(const float4*)(Bm + (long)(n0 + lrow + p*RPP) * ldb + k0 + lcol);
    };
    auto sts_tile = [&](int buf) {
        #pragma unroll
        for (int p = 0; p < PA; p++) {
            const int r = lrow + p*RPP;
            As[buf][r][lcol+0] = f2tf32(pa[p].x); As[buf][r][lcol+1] = f2tf32(pa[p].y);
            As[buf][r][lcol+2] = f2tf32(pa[p].z); As[buf][r][lcol+3] = f2tf32(pa[p].w);
        }
        #pragma unroll
        for (int p = 0; p < PB; p++) {
            const int r = lrow + p*RPP;
            Bs[buf][r][lcol+0] = f2tf32(pb[p].x); Bs[buf][r][lcol+1] = f2tf32(pb[p].y);
            Bs[buf][r][lcol+2] = f2tf32(pb[p].z); Bs[buf][r][lcol+3] = f2tf32(pb[p].w);
        }
    };

    float acc[MI][NI][4];
    #pragma unroll
    for (int i = 0; i < MI; i++)
        #pragma unroll
        for (int j = 0; j < NI; j++)
            #pragma unroll
            for (int r = 0; r < 4; r++) acc[i][j][r] = 0.0f;

    const int NKI = K / BK;
    ldg_tile(0);
    sts_tile(0);
    __syncthreads();

    for (int ki = 0; ki < NKI; ki++) {
        if (ki + 1 < NKI) ldg_tile((ki + 1) * BK);   // overlap with compute
        const int buf = ki & 1;
        const uint32_t as_base = (uint32_t)__cvta_generic_to_shared(&As[buf][0][0]);
        const uint32_t bs_base = (uint32_t)__cvta_generic_to_shared(&Bs[buf][0][0]);

        #pragma unroll
        for (int kk = 0; kk < BK; kk += 8) {
            uint32_t af[MI][4], bf[NI][2];
            #pragma unroll
            for (int i = 0; i < MI; i++) {
                const int mmx = wm*WTM + i*16 + lsel;
                ldsm_x4(af[i], as_base + (uint32_t)((mmx*STR + kk + ksel) << 2));
            }
            #pragma unroll
            for (int jj = 0; jj < NI/2; jj++) {
                const int nn = wn*WTN + jj*16 + lsel;
                uint32_t t[4];
                ldsm_x4(t, bs_base + (uint32_t)((nn*STR + kk + ksel) << 2));
                bf[2*jj  ][0] = t[0]; bf[2*jj+1][0] = t[1];
                bf[2*jj  ][1] = t[2]; bf[2*jj+1][1] = t[3];
            }
            #pragma unroll
            for (int i = 0; i < MI; i++)
                #pragma unroll
                for (int j = 0; j < NI; j++)
                    mma_tf32(acc[i][j], af[i], bf[j]);
        }

        if (ki + 1 < NKI) sts_tile((ki + 1) & 1);    // other buffer: safe (see header)
        __syncthreads();
    }

    #pragma unroll
    for (int i = 0; i < MI; i++) {
        #pragma unroll
        for (int j = 0; j < NI; j++) {
            const int mmx = m0 + wm*WTM + i*16 + lr;
            const int nn  = n0 + wn*WTN + j*8 + lc*2;
            float2 v0 = make_float2(acc[i][j][0], acc[i][j][1]);
            float2 v1 = make_float2(acc[i][j][2], acc[i][j][3]);
            const float2 bb = *(const float2*)(bias + nn);
            v0.x += bb.x; v0.y += bb.y;
            v1.x += bb.x; v1.y += bb.y;
            *(float2*)(C + (long)mmx * ldc + nn)     = v0;
            *(float2*)(C + (long)(mmx+8) * ldc + nn) = v1;
        }
    }
}

// ---------------------------------------------------------------------------
// Fused flash attention with graph mask.
// vs R14: P goes through smem (Ps, rna-tf32 at STS -> bit-identical numerics)
// and is reloaded as A-fragments via ldmatrix; the 144-slot shuffle transpose
// is gone. K/V single-buffered; each buffer's prefetch (cp.async) is issued
// immediately after its last-reader barrier: K(kt+1) after the post-S sync
// (overlaps softmax+PV), V(kt+1) after the post-PV sync.
// Smem: Q 128x68 + K 64x68 + V 64x72 + P 128x68 = 103 KB -> 2 CTAs/SM.
// ---------------------------------------------------------------------------
#define FL_SMEM ((128*68 + 64*68 + 64*72 + 128*68) * 4)

__global__ void __launch_bounds__(256, 2)
flash_kernel(const float* __restrict__ qkv, const unsigned* __restrict__ adj,
             float* __restrict__ attn_out)
{
    extern __shared__ uint32_t smf[];
    uint32_t (*Qs)[68] = (uint32_t(*)[68])(smf);                          // [qrow][hd]
    uint32_t (*Ks)[68] = (uint32_t(*)[68])(smf + 128*68);                 // [key][hd]
    uint32_t (*Vs)[72] = (uint32_t(*)[72])(smf + 128*68 + 64*68);         // [key][hd]
    uint32_t (*Ps)[68] = (uint32_t(*)[68])(smf + 128*68 + 64*68 + 64*72); // [qrow][key]

    const int q0 = blockIdx.x * 128;
    const int b  = blockIdx.y / H_;
    const int h  = blockIdx.y % H_;

    const int tid  = threadIdx.x;
    const int wid  = tid >> 5;
    const int lane = tid & 31;
    const int lr   = lane >> 2;
    const int lc   = lane & 3;
    const int mm   = wid * 16;
    const int lsel = (lane & 15);
    const int ksel = (lane >> 4) << 2;

    const uint32_t qs_base = (uint32_t)__cvta_generic_to_shared(&Qs[0][0]);
    const uint32_t ks_base = (uint32_t)__cvta_generic_to_shared(&Ks[0][0]);
    const uint32_t ps_base = (uint32_t)__cvta_generic_to_shared(&Ps[0][0]);

    const float* qb = qkv + (long)b*L_*D3_ + h*HD_;
    const float* kb = qb + D_;
    const float* vb = qb + 2*D_;

    // K-tile / V-tile cp.async loaders (each its own commit group)
    auto load_k = [&](int kbase) {
        #pragma unroll
        for (int p = 0; p < 4; p++) {
            const int c = tid + 256*p;
            const int r = c >> 4;
            const int w = (c & 15) * 4;
            cp_async16(&Ks[r][w], kb + (long)(kbase + r) * D3_ + w);
        }
        cp_commit();
    };
    auto load_v = [&](int kbase) {
        #pragma unroll
        for (int p = 0; p < 4; p++) {
            const int c = tid + 256*p;
            const int r = c >> 4;
            const int w = (c & 15) * 4;
            cp_async16(&Vs[r][w], vb + (long)(kbase + r) * D3_ + w);
        }
        cp_commit();
    };

    load_k(0);
    load_v(0);

    // ---- Q tile (pre-scaled by 1/8, rna tf32)
    {
        const int r  = tid >> 4;
        const int c4 = (tid & 15) * 4;
        #pragma unroll
        for (int p = 0; p < 8; p++) {
            const float4 v = *(const float4*)(qb + (long)(q0 + r + p*16)*D3_ + c4);
            Qs[r+p*16][c4+0] = f2tf32(v.x * 0.125f);
            Qs[r+p*16][c4+1] = f2tf32(v.y * 0.125f);
            Qs[r+p*16][c4+2] = f2tf32(v.z * 0.125f);
            Qs[r+p*16][c4+3] = f2tf32(v.w * 0.125f);
        }
    }

    const int r0g = q0 + mm + lr;
    const int r1g = r0g + 8;
    const unsigned* adj0 = adj + (long)r0g * ADJW;
    const unsigned* adj1 = adj + (long)r1g * ADJW;

    float o[8][4];
    #pragma unroll
    for (int j = 0; j < 8; j++)
        #pragma unroll
        for (int r = 0; r < 4; r++) o[j][r] = 0.0f;
    float m0 = -INFINITY, m1 = -INFINITY, l0 = 0.0f, l1 = 0.0f;

    for (int kt = 0; kt < 16; kt++) {
        cp_wait<0>();
        __syncthreads();          // K(kt), V(kt) resident; all warps past prior PV

        // ---- S = (Q/8) K^T : warp tile 16 x 64, ldmatrix fragments
        float sc[8][4];
        #pragma unroll
        for (int j = 0; j < 8; j++)
            #pragma unroll
            for (int r = 0; r < 4; r++) sc[j][r] = 0.0f;

        #pragma unroll
        for (int kk = 0; kk < 64; kk += 8) {
            uint32_t af[4];
            ldsm_x4(af, qs_base + (uint32_t)(((mm + lsel)*68 + kk + ksel) << 2));
            #pragma unroll
            for (int jj = 0; jj < 4; jj++) {
                uint32_t t[4];
                ldsm_x4(t, ks_base + (uint32_t)(((16*jj + lsel)*68 + kk + ksel) << 2));
                uint32_t bf0[2] = {t[0], t[2]};
                uint32_t bf1[2] = {t[1], t[3]};
                mma_tf32(sc[2*jj  ], af, bf0);
                mma_tf32(sc[2*jj+1], af, bf1);
            }
        }

        __syncthreads();          // all warps done reading Ks
        if (kt + 1 < 16) load_k((kt + 1) * 64);   // overlaps softmax + PV

        // ---- mask + online softmax (rows lr / lr+8)
        const unsigned wA0 = adj0[2*kt], wA1 = adj0[2*kt+1];
        const unsigned wB0 = adj1[2*kt], wB1 = adj1[2*kt+1];
        float tm0 = -INFINITY, tm1 = -INFINITY;
        unsigned mk = 0;
        #pragma unroll
        for (int j = 0; j < 8; j++) {
            const int cbit = (8*j + 2*lc) & 31;
            const unsigned wa = (j < 4) ? wA0 : wA1;
            const unsigned wb = (j < 4) ? wB0 : wB1;
            const unsigned f00 = (wa >> cbit) & 1u;
            const unsigned f01 = (wa >> (cbit+1)) & 1u;
            const unsigned f10 = (wb >> cbit) & 1u;
            const unsigned f11 = (wb >> (cbit+1)) & 1u;
            mk |= (f00 | (f01 << 1) | (f10 << 2) | (f11 << 3)) << (4*j);
            if (!f00) tm0 = fmaxf(tm0, sc[j][0]);
            if (!f01) tm0 = fmaxf(tm0, sc[j][1]);
            if (!f10) tm1 = fmaxf(tm1, sc[j][2]);
            if (!f11) tm1 = fmaxf(tm1, sc[j][3]);
        }
        tm0 = fmaxf(tm0, __shfl_xor_sync(0xFFFFFFFFu, tm0, 1));
        tm0 = fmaxf(tm0, __shfl_xor_sync(0xFFFFFFFFu, tm0, 2));
        tm1 = fmaxf(tm1, __shfl_xor_sync(0xFFFFFFFFu, tm1, 1));
        tm1 = fmaxf(tm1, __shfl_xor_sync(0xFFFFFFFFu, tm1, 2));

        const float mn0 = fmaxf(m0, tm0);
        const float mn1 = fmaxf(m1, tm1);
        const float a0 = (m0 == -INFINITY) ? 0.0f : __expf(m0 - mn0);
        const float a1 = (m1 == -INFINITY) ? 0.0f : __expf(m1 - mn1);
        m0 = mn0; m1 = mn1;

        float rs0 = 0.0f, rs1 = 0.0f;
        #pragma unroll
        for (int j = 0; j < 8; j++) {
            const unsigned mj = mk >> (4*j);
            const float p0 = (mj & 1u) ? 0.0f : __expf(sc[j][0] - mn0);
            const float p1 = (mj & 2u) ? 0.0f : __expf(sc[j][1] - mn0);
            const float p2 = (mj & 4u) ? 0.0f : __expf(sc[j][2] - mn1);
            const float p3 = (mj & 8u) ? 0.0f : __expf(sc[j][3] - mn1);
            rs0 += p0 + p1;
            rs1 += p2 + p3;
            // P -> smem (rna tf32, same values as before -> bit-identical)
            uint2 w0; w0.x = f2tf32(p0); w0.y = f2tf32(p1);
            uint2 w1; w1.x = f2tf32(p2); w1.y = f2tf32(p3);
            *(uint2*)&Ps[mm+lr  ][8*j+2*lc] = w0;
            *(uint2*)&Ps[mm+lr+8][8*j+2*lc] = w1;
        }
        rs0 += __shfl_xor_sync(0xFFFFFFFFu, rs0, 1);
        rs0 += __shfl_xor_sync(0xFFFFFFFFu, rs0, 2);
        rs1 += __shfl_xor_sync(0xFFFFFFFFu, rs1, 1);
        rs1 += __shfl_xor_sync(0xFFFFFFFFu, rs1, 2);
        l0 = a0*l0 + rs0;
        l1 = a1*l1 + rs1;

        #pragma unroll
        for (int j = 0; j < 8; j++) {
            o[j][0] *= a0; o[j][1] *= a0;
            o[j][2] *= a1; o[j][3] *= a1;
        }

        __syncwarp();             // Ps rows are warp-private: STS -> LDSM visibility

        // ---- O += P V : ldmatrix A-frags from Ps, V scalar B-frags
        #pragma unroll
        for (int kk = 0; kk < 64; kk += 8) {
            uint32_t af[4];
            ldsm_x4(af, ps_base + (uint32_t)(((mm + lsel)*68 + kk + ksel) << 2));
            #pragma unroll
            for (int j = 0; j < 8; j++) {
                uint32_t bf[2];
                bf[0] = Vs[kk+lc  ][8*j+lr];
                bf[1] = Vs[kk+lc+4][8*j+lr];
                mma_tf32(o[j], af, bf);
            }
        }

        __syncthreads();          // all warps done reading Vs
        if (kt + 1 < 16) load_v((kt + 1) * 64);
    }

    // ---- epilogue
    const float i0 = 1.0f / l0;
    const float i1 = 1.0f / l1;
    float* ob = attn_out + (long)b*L_*D_ + h*HD_;
    #pragma unroll
    for (int j = 0; j < 8; j++) {
        const int nn = 8*j + 2*lc;
        *(float2*)(ob + (long)r0g*D_ + nn) = make_float2(o[j][0]*i0, o[j][1]*i0);
        *(float2*)(ob + (long)r1g*D_ + nn) = make_float2(o[j][2]*i1, o[j][3]*i1);
    }
}

// ---------------------------------------------------------------------------
// Launch
// ---------------------------------------------------------------------------
extern "C" void kernel_launch(void* const* d_in, const int* in_sizes, int n_in,
                              void* d_out, int out_size)
{
    const float* x     = (const float*)d_in[0];
    const int*   edges = (const int*)  d_in[1];
    const float* w_qkv = (const float*)d_in[2];
    const float* b_qkv = (const float*)d_in[3];
    const float* w_out = (const float*)d_in[4];
    const float* b_out = (const float*)d_in[5];
    float* out = (float*)d_out;
    const int E = in_sizes[1] / 2;

    float *qkv, *attn; unsigned* adj;
    cudaGetSymbolAddress((void**)&qkv,  g_qkv);
    cudaGetSymbolAddress((void**)&attn, g_attn);
    cudaGetSymbolAddress((void**)&adj,  g_adj);

    static int smem_set = 0;
    if (!smem_set) {
        cudaFuncSetAttribute(flash_kernel,
                             cudaFuncAttributeMaxDynamicSharedMemorySize, FL_SMEM);
        smem_set = 1;
    }

    // 1) adjacency bitmask
    zero_adj_kernel<<<(L_*ADJW + 255) / 256, 256>>>(adj);
    build_adj_kernel<<<(E + 255) / 256, 256>>>(adj, edges, E);

    // 2) QKV projection: [4096,3072] = X[4096,1024] @ Wqkv[3072,1024]^T + b
    {
        dim3 g(D3_/128, (B_*L_)/128);
        gemm_tc<128,128,16,2,4><<<g, 256>>>(
            x, w_qkv, b_qkv, qkv, D_, D_, D3_, D_);
    }

    // 3) fused masked attention (scores never materialized)
    {
        dim3 g(L_/128, B_*H_);
        flash_kernel<<<g, 256, FL_SMEM>>>(qkv, adj, attn);
    }

    // 4) out projection: [4096,1024] = attn[4096,1024] @ Wout[1024,1024]^T + b
    {
        dim3 g(D_/128, (B_*L_)/128);
        gemm_tc<128,128,16,2,4><<<g, 256>>>(
            attn, w_out, b_out, out, D_, D_, D_, D_);
    }
}